// round 1
// baseline (speedup 1.0000x reference)
#include <cuda_runtime.h>

#define NPHI 128
#define DEG  127

typedef unsigned long long u64;

// Coefficients C_j of a(w) = w^{-127} * sum_j C_j * (w^2)^j  (complex, 128 entries)
__device__ float2 g_coefA[NPHI];

// ---------------------------------------------------------------------------
// Kernel 1: build the 128 complex coefficients from the phis (one block).
// Recurrence over k = 1..127 (with z = w^2, arrays padded so index j-1 -> [j]):
//   A'[j] = e_k     * 0.5*((A[j-1] + A[j]) + (B[j-1] - B[j]))
//   B'[j] = conj(e_k)*0.5*((A[j-1] - A[j]) + (B[j-1] + B[j]))
// Init: A[0] = e_0, everything else 0. Map on (A,B) is pointwise-unitary on the
// unit circle => coefficient l2 norm preserved => numerically stable in fp32.
// ---------------------------------------------------------------------------
__global__ void qsp_coeff_kernel(const float* __restrict__ phis) {
    __shared__ float er[NPHI], ei[NPHI];
    __shared__ float Ar[2][NPHI + 1], Ai[2][NPHI + 1];
    __shared__ float Br[2][NPHI + 1], Bi[2][NPHI + 1];
    int j = threadIdx.x;  // 0..127

    float s, c;
    sincosf(phis[j], &s, &c);
    er[j] = c; ei[j] = s;

    Ar[0][j + 1] = 0.f; Ai[0][j + 1] = 0.f;
    Br[0][j + 1] = 0.f; Bi[0][j + 1] = 0.f;
    Ar[1][j + 1] = 0.f; Ai[1][j + 1] = 0.f;
    Br[1][j + 1] = 0.f; Bi[1][j + 1] = 0.f;
    if (j == 0) {
        Ar[0][0] = Ai[0][0] = Br[0][0] = Bi[0][0] = 0.f;
        Ar[1][0] = Ai[1][0] = Br[1][0] = Bi[1][0] = 0.f;
    }
    __syncthreads();
    if (j == 0) { Ar[0][1] = er[0]; Ai[0][1] = ei[0]; }  // A_0 = e^{i phi_0}
    __syncthreads();

    int p = 0;
    for (int k = 1; k <= DEG; k++) {
        int q = p ^ 1;
        float am1r = Ar[p][j],     am1i = Ai[p][j];
        float a0r  = Ar[p][j + 1], a0i  = Ai[p][j + 1];
        float bm1r = Br[p][j],     bm1i = Bi[p][j];
        float b0r  = Br[p][j + 1], b0i  = Bi[p][j + 1];

        float tAr = 0.5f * (am1r + a0r + bm1r - b0r);
        float tAi = 0.5f * (am1i + a0i + bm1i - b0i);
        float tBr = 0.5f * (am1r - a0r + bm1r + b0r);
        float tBi = 0.5f * (am1i - a0i + bm1i + b0i);

        float ekr = er[k], eki = ei[k];
        Ar[q][j + 1] = ekr * tAr - eki * tAi;   // e_k * tA
        Ai[q][j + 1] = ekr * tAi + eki * tAr;
        Br[q][j + 1] = ekr * tBr + eki * tBi;   // conj(e_k) * tB
        Bi[q][j + 1] = ekr * tBi - eki * tBr;

        p = q;
        __syncthreads();
    }
    g_coefA[j] = make_float2(Ar[p][j + 1], Ai[p][j + 1]);
}

// ---------------------------------------------------------------------------
// Packed f32x2 helpers (FFMA2 — only reachable via PTX fma.rn.f32x2)
// ---------------------------------------------------------------------------
__device__ __forceinline__ u64 pk2(float lo, float hi) {
    u64 r; asm("mov.b64 %0,{%1,%2};" : "=l"(r) : "f"(lo), "f"(hi)); return r;
}
__device__ __forceinline__ void upk2(u64 v, float& lo, float& hi) {
    asm("mov.b64 {%0,%1},%2;" : "=f"(lo), "=f"(hi) : "l"(v));
}
__device__ __forceinline__ u64 ffma2(u64 a, u64 b, u64 c) {
    u64 d; asm("fma.rn.f32x2 %0,%1,%2,%3;" : "=l"(d) : "l"(a), "l"(b), "l"(c)); return d;
}

// ---------------------------------------------------------------------------
// Kernel 2: per-theta evaluation. Each thread handles TWO thetas packed into
// the two lanes of f32x2 registers. Horner over z = e^{2i theta}, then
// multiply by w̄^127 (square-and-multiply, 127 = 0b1111111 -> 6 sq + 6 mul).
// ---------------------------------------------------------------------------
__global__ void __launch_bounds__(256) qsp_main_kernel(const float* __restrict__ th,
                                                       float* __restrict__ out, int B) {
    __shared__ u64 sCr[NPHI], sCi[NPHI];  // coefficients duplicated into both lanes
    int t = threadIdx.x;
    if (t < NPHI) {
        float2 cc = g_coefA[t];
        sCr[t] = pk2(cc.x, cc.x);
        sCi[t] = pk2(cc.y, cc.y);
    }
    __syncthreads();

    int i = 2 * (blockIdx.x * blockDim.x + t);
    if (i + 1 >= B) return;

    float2 tt = *(const float2*)(th + i);
    float s0, c0, s1, c1;
    sincosf(tt.x, &s0, &c0);
    sincosf(tt.y, &s1, &c1);

    // z = w^2 = e^{2i theta}
    float zr0 = c0 * c0 - s0 * s0, zi0 = 2.f * c0 * s0;
    float zr1 = c1 * c1 - s1 * s1, zi1 = 2.f * c1 * s1;

    // w̄^127 per lane: r = v; 6x { v = v^2; r = r*v; }  => r = v^127
    float vr0 = c0, vi0 = -s0, rr0 = vr0, ri0 = vi0;
    float vr1 = c1, vi1 = -s1, rr1 = vr1, ri1 = vi1;
#pragma unroll
    for (int q = 0; q < 6; q++) {
        float n0r = vr0 * vr0 - vi0 * vi0, n0i = 2.f * vr0 * vi0;
        vr0 = n0r; vi0 = n0i;
        float m0r = rr0 * vr0 - ri0 * vi0, m0i = rr0 * vi0 + ri0 * vr0;
        rr0 = m0r; ri0 = m0i;
        float n1r = vr1 * vr1 - vi1 * vi1, n1i = 2.f * vr1 * vi1;
        vr1 = n1r; vi1 = n1i;
        float m1r = rr1 * vr1 - ri1 * vi1, m1i = rr1 * vi1 + ri1 * vr1;
        rr1 = m1r; ri1 = m1i;
    }

    // Packed complex Horner: acc = C[127]; acc = acc*z + C[j]
    u64 ZR  = pk2(zr0, zr1);
    u64 ZI  = pk2(zi0, zi1);
    u64 NZI = pk2(-zi0, -zi1);
    u64 AR = sCr[DEG], AI = sCi[DEG];
#pragma unroll 8
    for (int j = DEG - 1; j >= 0; j--) {
        u64 nAR = ffma2(AR, ZR, ffma2(AI, NZI, sCr[j]));
        u64 nAI = ffma2(AR, ZI, ffma2(AI, ZR, sCi[j]));
        AR = nAR; AI = nAI;
    }

    float ar0, ar1, ai0, ai1;
    upk2(AR, ar0, ar1);
    upk2(AI, ai0, ai1);

    // a = acc * w̄^127
    float re0 = ar0 * rr0 - ai0 * ri0, im0 = ar0 * ri0 + ai0 * rr0;
    float re1 = ar1 * rr1 - ai1 * ri1, im1 = ar1 * ri1 + ai1 * rr1;

    *(float2*)(out + i)     = make_float2(re0, re1);   // real part block
    *(float2*)(out + B + i) = make_float2(im0, im1);   // imag part block
}

extern "C" void kernel_launch(void* const* d_in, const int* in_sizes, int n_in,
                              void* d_out, int out_size) {
    const float* th   = (const float*)d_in[0];
    const float* phis = (const float*)d_in[1];
    float* out = (float*)d_out;
    int B = in_sizes[0];

    qsp_coeff_kernel<<<1, NPHI>>>(phis);

    int nthreads = (B + 1) / 2;                 // 2 thetas per thread
    int blocks = (nthreads + 255) / 256;
    qsp_main_kernel<<<blocks, 256>>>(th, out, B);
}

// round 4
// speedup vs baseline: 1.1348x; 1.1348x over previous
#include <cuda_runtime.h>

#define NPHI 128
#define DEG  127

typedef unsigned long long u64;

// Coefficients C_j of a(w) = w^{-127} * sum_j C_j * (w^2)^j  (complex, 128 entries)
__device__ float2 g_coefA[NPHI];

// ---------------------------------------------------------------------------
// Kernel 1: build the 128 complex coefficients from the phis (one block).
// Pointwise-unitary recurrence => coefficient l2-norm preserved => stable fp32.
// ---------------------------------------------------------------------------
__global__ void qsp_coeff_kernel(const float* __restrict__ phis) {
    __shared__ float er[NPHI], ei[NPHI];
    __shared__ float Ar[2][NPHI + 1], Ai[2][NPHI + 1];
    __shared__ float Br[2][NPHI + 1], Bi[2][NPHI + 1];
    int j = threadIdx.x;  // 0..127

    float s, c;
    sincosf(phis[j], &s, &c);
    er[j] = c; ei[j] = s;

    Ar[0][j + 1] = 0.f; Ai[0][j + 1] = 0.f;
    Br[0][j + 1] = 0.f; Bi[0][j + 1] = 0.f;
    Ar[1][j + 1] = 0.f; Ai[1][j + 1] = 0.f;
    Br[1][j + 1] = 0.f; Bi[1][j + 1] = 0.f;
    if (j == 0) {
        Ar[0][0] = Ai[0][0] = Br[0][0] = Bi[0][0] = 0.f;
        Ar[1][0] = Ai[1][0] = Br[1][0] = Bi[1][0] = 0.f;
    }
    __syncthreads();
    if (j == 0) { Ar[0][1] = er[0]; Ai[0][1] = ei[0]; }  // A_0 = e^{i phi_0}
    __syncthreads();

    int p = 0;
    for (int k = 1; k <= DEG; k++) {
        int q = p ^ 1;
        float am1r = Ar[p][j],     am1i = Ai[p][j];
        float a0r  = Ar[p][j + 1], a0i  = Ai[p][j + 1];
        float bm1r = Br[p][j],     bm1i = Bi[p][j];
        float b0r  = Br[p][j + 1], b0i  = Bi[p][j + 1];

        float tAr = 0.5f * (am1r + a0r + bm1r - b0r);
        float tAi = 0.5f * (am1i + a0i + bm1i - b0i);
        float tBr = 0.5f * (am1r - a0r + bm1r + b0r);
        float tBi = 0.5f * (am1i - a0i + bm1i + b0i);

        float ekr = er[k], eki = ei[k];
        Ar[q][j + 1] = ekr * tAr - eki * tAi;   // e_k * tA
        Ai[q][j + 1] = ekr * tAi + eki * tAr;
        Br[q][j + 1] = ekr * tBr + eki * tBi;   // conj(e_k) * tB
        Bi[q][j + 1] = ekr * tBi - eki * tBr;

        p = q;
        __syncthreads();
    }
    g_coefA[j] = make_float2(Ar[p][j + 1], Ai[p][j + 1]);
}

// ---------------------------------------------------------------------------
// Packed f32x2 helpers (FFMA2 only reachable via PTX fma.rn.f32x2)
// ---------------------------------------------------------------------------
__device__ __forceinline__ u64 pk2(float lo, float hi) {
    u64 r; asm("mov.b64 %0,{%1,%2};" : "=l"(r) : "f"(lo), "f"(hi)); return r;
}
__device__ __forceinline__ void upk2(u64 v, float& lo, float& hi) {
    asm("mov.b64 {%0,%1},%2;" : "=f"(lo), "=f"(hi) : "l"(v));
}
__device__ __forceinline__ u64 ffma2(u64 a, u64 b, u64 c) {
    u64 d; asm("fma.rn.f32x2 %0,%1,%2,%3;" : "=l"(d) : "l"(a), "l"(b), "l"(c)); return d;
}
__device__ __forceinline__ u64 fmul2(u64 a, u64 b) {
    u64 d; asm("mul.rn.f32x2 %0,%1,%2;" : "=l"(d) : "l"(a), "l"(b)); return d;
}
__device__ __forceinline__ u64 neg2(u64 a) {
    return a ^ 0x8000000080000000ULL;  // flip both fp32 sign bits
}
// One LDS.128 -> two u64 (coefficient pair)
__device__ __forceinline__ void lds_v2b64(u64& a, u64& b, unsigned saddr) {
    asm volatile("ld.shared.v2.b64 {%0,%1},[%2];" : "=l"(a), "=l"(b) : "r"(saddr));
}
// packed complex multiply: (ar,ai)*(br,bi)
__device__ __forceinline__ void cmul2(u64& rr, u64& ri, u64 ar, u64 ai, u64 br, u64 bi) {
    rr = ffma2(ar, br, neg2(fmul2(ai, bi)));
    ri = ffma2(ar, bi, fmul2(ai, br));
}

// ---------------------------------------------------------------------------
// Kernel 2: per-theta evaluation. 4 thetas per thread = TWO independent
// packed (f32x2) Horner chains sharing one coefficient LDS.128 per step.
// Horner over z = e^{2i theta}; epilogue multiplies by
// w̄^127 = conj(w) * conj(z)^63 (conj(z) is free: we hold ZR and -ZI).
// ---------------------------------------------------------------------------
__global__ void __launch_bounds__(256) qsp_main_kernel(const float* __restrict__ th,
                                                       float* __restrict__ out, int B) {
    __shared__ __align__(16) u64 sC[2 * NPHI];  // interleaved (CR, CI), lanes duplicated
    int t = threadIdx.x;
    if (t < NPHI) {
        float2 cc = g_coefA[t];
        sC[2 * t]     = pk2(cc.x, cc.x);
        sC[2 * t + 1] = pk2(cc.y, cc.y);
    }
    __syncthreads();

    unsigned sbase = (unsigned)__cvta_generic_to_shared(sC);

    int base = (blockIdx.x * blockDim.x + t) * 4;
    if (base + 3 >= B + 3) return;  // (B is a multiple of 4; keep a cheap guard)

    float4 T = *(const float4*)(th + base);
    float s0, c0, s1, c1, s2, c2, s3, c3;
    sincosf(T.x, &s0, &c0);
    sincosf(T.y, &s1, &c1);
    sincosf(T.z, &s2, &c2);
    sincosf(T.w, &s3, &c3);

    // chain a: thetas 0,1 ; chain b: thetas 2,3
    u64 ZRa  = pk2(c0 * c0 - s0 * s0, c1 * c1 - s1 * s1);
    u64 ZIa  = pk2(2.f * c0 * s0,     2.f * c1 * s1);
    u64 ZRb  = pk2(c2 * c2 - s2 * s2, c3 * c3 - s3 * s3);
    u64 ZIb  = pk2(2.f * c2 * s2,     2.f * c3 * s3);
    u64 NZIa = neg2(ZIa);
    u64 NZIb = neg2(ZIb);
    // conj(w) for epilogue
    u64 CWRa = pk2(c0, c1), CWIa = pk2(-s0, -s1);
    u64 CWRb = pk2(c2, c3), CWIb = pk2(-s2, -s3);

    u64 ARa, AIa, ARb, AIb;
    lds_v2b64(ARa, AIa, sbase + 16u * DEG);
    ARb = ARa; AIb = AIa;

#pragma unroll 8
    for (int j = DEG - 1; j >= 0; j--) {
        u64 CR, CI;
        lds_v2b64(CR, CI, sbase + 16u * (unsigned)j);
        u64 nARa = ffma2(ARa, ZRa, ffma2(AIa, NZIa, CR));
        u64 nAIa = ffma2(ARa, ZIa, ffma2(AIa, ZRa, CI));
        u64 nARb = ffma2(ARb, ZRb, ffma2(AIb, NZIb, CR));
        u64 nAIb = ffma2(ARb, ZIb, ffma2(AIb, ZRb, CI));
        ARa = nARa; AIa = nAIa;
        ARb = nARb; AIb = nAIb;
    }

    // epilogue: m = conj(w) * conj(z)^63 ; result = A * m
    // conj(z) = (ZR, NZI). 63 = 111111b -> r=v; 5x { v=v^2; r=r*v }
    u64 VRa = ZRa, VIa = NZIa, RRa = ZRa, RIa = NZIa;
    u64 VRb = ZRb, VIb = NZIb, RRb = ZRb, RIb = NZIb;
#pragma unroll
    for (int q = 0; q < 5; q++) {
        u64 nvr, nvi;
        cmul2(nvr, nvi, VRa, VIa, VRa, VIa); VRa = nvr; VIa = nvi;
        cmul2(nvr, nvi, RRa, RIa, VRa, VIa); RRa = nvr; RIa = nvi;
        cmul2(nvr, nvi, VRb, VIb, VRb, VIb); VRb = nvr; VIb = nvi;
        cmul2(nvr, nvi, RRb, RIb, VRb, VIb); RRb = nvr; RIb = nvi;
    }
    // m = conj(w) * R
    u64 MRa, MIa, MRb, MIb;
    cmul2(MRa, MIa, CWRa, CWIa, RRa, RIa);
    cmul2(MRb, MIb, CWRb, CWIb, RRb, RIb);
    // final = A * M
    u64 FRa, FIa, FRb, FIb;
    cmul2(FRa, FIa, ARa, AIa, MRa, MIa);
    cmul2(FRb, FIb, ARb, AIb, MRb, MIb);

    float r0, r1, r2, r3, i0, i1, i2, i3;
    upk2(FRa, r0, r1); upk2(FRb, r2, r3);
    upk2(FIa, i0, i1); upk2(FIb, i2, i3);

    *(float4*)(out + base)     = make_float4(r0, r1, r2, r3);  // real block
    *(float4*)(out + B + base) = make_float4(i0, i1, i2, i3);  // imag block
}

extern "C" void kernel_launch(void* const* d_in, const int* in_sizes, int n_in,
                              void* d_out, int out_size) {
    const float* th   = (const float*)d_in[0];
    const float* phis = (const float*)d_in[1];
    float* out = (float*)d_out;
    int B = in_sizes[0];

    qsp_coeff_kernel<<<1, NPHI>>>(phis);

    int nthreads = (B + 3) / 4;                 // 4 thetas per thread
    int blocks = (nthreads + 255) / 256;
    qsp_main_kernel<<<blocks, 256>>>(th, out, B);
}

// round 7
// speedup vs baseline: 1.2390x; 1.0919x over previous
#include <cuda_runtime.h>

#define NPHI 128
#define DEG  127

typedef unsigned long long u64;

// Coefficients C_j of a(w) = w^{-127} * sum_j C_j * (w^2)^j  (complex, 128 entries)
__device__ float2 g_coefA[NPHI];

// ---------------------------------------------------------------------------
// Kernel 1: build the 128 complex coefficients from the phis (one block).
// Pointwise-unitary recurrence => coefficient l2-norm preserved => stable fp32.
// ---------------------------------------------------------------------------
__global__ void qsp_coeff_kernel(const float* __restrict__ phis) {
    __shared__ float er[NPHI], ei[NPHI];
    __shared__ float Ar[2][NPHI + 1], Ai[2][NPHI + 1];
    __shared__ float Br[2][NPHI + 1], Bi[2][NPHI + 1];
    int j = threadIdx.x;  // 0..127

    float s, c;
    sincosf(phis[j], &s, &c);
    er[j] = c; ei[j] = s;

    Ar[0][j + 1] = 0.f; Ai[0][j + 1] = 0.f;
    Br[0][j + 1] = 0.f; Bi[0][j + 1] = 0.f;
    Ar[1][j + 1] = 0.f; Ai[1][j + 1] = 0.f;
    Br[1][j + 1] = 0.f; Bi[1][j + 1] = 0.f;
    if (j == 0) {
        Ar[0][0] = Ai[0][0] = Br[0][0] = Bi[0][0] = 0.f;
        Ar[1][0] = Ai[1][0] = Br[1][0] = Bi[1][0] = 0.f;
    }
    __syncthreads();
    if (j == 0) { Ar[0][1] = er[0]; Ai[0][1] = ei[0]; }  // A_0 = e^{i phi_0}
    __syncthreads();

    int p = 0;
    for (int k = 1; k <= DEG; k++) {
        int q = p ^ 1;
        float am1r = Ar[p][j],     am1i = Ai[p][j];
        float a0r  = Ar[p][j + 1], a0i  = Ai[p][j + 1];
        float bm1r = Br[p][j],     bm1i = Bi[p][j];
        float b0r  = Br[p][j + 1], b0i  = Bi[p][j + 1];

        float tAr = 0.5f * (am1r + a0r + bm1r - b0r);
        float tAi = 0.5f * (am1i + a0i + bm1i - b0i);
        float tBr = 0.5f * (am1r - a0r + bm1r + b0r);
        float tBi = 0.5f * (am1i - a0i + bm1i + b0i);

        float ekr = er[k], eki = ei[k];
        Ar[q][j + 1] = ekr * tAr - eki * tAi;   // e_k * tA
        Ai[q][j + 1] = ekr * tAi + eki * tAr;
        Br[q][j + 1] = ekr * tBr + eki * tBi;   // conj(e_k) * tB
        Bi[q][j + 1] = ekr * tBi - eki * tBr;

        p = q;
        __syncthreads();
    }
    g_coefA[j] = make_float2(Ar[p][j + 1], Ai[p][j + 1]);
}

// ---------------------------------------------------------------------------
// Packed f32x2 helpers
// ---------------------------------------------------------------------------
__device__ __forceinline__ u64 pk2(float lo, float hi) {
    u64 r; asm("mov.b64 %0,{%1,%2};" : "=l"(r) : "f"(lo), "f"(hi)); return r;
}
__device__ __forceinline__ void upk2(u64 v, float& lo, float& hi) {
    asm("mov.b64 {%0,%1},%2;" : "=f"(lo), "=f"(hi) : "l"(v));
}
__device__ __forceinline__ u64 ffma2(u64 a, u64 b, u64 c) {
    u64 d; asm("fma.rn.f32x2 %0,%1,%2,%3;" : "=l"(d) : "l"(a), "l"(b), "l"(c)); return d;
}
__device__ __forceinline__ u64 fmul2(u64 a, u64 b) {
    u64 d; asm("mul.rn.f32x2 %0,%1,%2;" : "=l"(d) : "l"(a), "l"(b)); return d;
}
__device__ __forceinline__ u64 fsub2(u64 a, u64 b) {
    u64 d; asm("sub.rn.f32x2 %0,%1,%2;" : "=l"(d) : "l"(a), "l"(b)); return d;
}
__device__ __forceinline__ u64 neg2(u64 a) {
    return a ^ 0x8000000080000000ULL;  // flip both fp32 sign bits
}
// One LDS.128 -> two u64 (coefficient pair)
__device__ __forceinline__ void lds_v2b64(u64& a, u64& b, unsigned saddr) {
    asm volatile("ld.shared.v2.b64 {%0,%1},[%2];" : "=l"(a), "=l"(b) : "r"(saddr));
}
// packed complex multiply: (ar,ai)*(br,bi)
__device__ __forceinline__ void cmul2(u64& rr, u64& ri, u64 ar, u64 ai, u64 br, u64 bi) {
    rr = ffma2(ar, br, neg2(fmul2(ai, bi)));
    ri = ffma2(ar, bi, fmul2(ai, br));
}

// ---------------------------------------------------------------------------
// Kernel 2: 4 thetas per thread = two independent packed (f32x2) GOERTZEL
// chains sharing one coefficient LDS.128 per step.
//   P(z) = sum_j C_j z^j,  z = e^{2i theta}:
//     b_k = C_k + 2*Re(z)*b_{k+1} - b_{k+2}   (real multiplier!)
//     P   = b_0 - conj(z)*b_1
// Complex state splits into two REAL recurrences (SUB2 rt2 + FFMA2 rt3 per
// component) vs complex Horner's 2xFFMA2 rt3 -> 10 vs 12 RF-bank cycles/coeff.
// Epilogue multiplies by w^-127 = conj(w) * conj(z)^63.
// ---------------------------------------------------------------------------
__global__ void __launch_bounds__(256) qsp_main_kernel(const float* __restrict__ th,
                                                       float* __restrict__ out, int B) {
    __shared__ __align__(16) u64 sC[2 * NPHI];  // interleaved (CR, CI), lanes duplicated
    int t = threadIdx.x;
    if (t < NPHI) {
        float2 cc = g_coefA[t];
        sC[2 * t]     = pk2(cc.x, cc.x);
        sC[2 * t + 1] = pk2(cc.y, cc.y);
    }
    __syncthreads();

    unsigned sbase = (unsigned)__cvta_generic_to_shared(sC);

    int base = (blockIdx.x * blockDim.x + t) * 4;
    if (base + 3 >= B + 3) return;  // B multiple of 4; cheap guard

    float4 T = *(const float4*)(th + base);
    float s0, c0, s1, c1, s2, c2, s3, c3;
    __sincosf(T.x, &s0, &c0);
    __sincosf(T.y, &s1, &c1);
    __sincosf(T.z, &s2, &c2);
    __sincosf(T.w, &s3, &c3);

    // z = e^{2i theta}
    float zr0 = c0 * c0 - s0 * s0, zi0 = 2.f * c0 * s0;
    float zr1 = c1 * c1 - s1 * s1, zi1 = 2.f * c1 * s1;
    float zr2 = c2 * c2 - s2 * s2, zi2 = 2.f * c2 * s2;
    float zr3 = c3 * c3 - s3 * s3, zi3 = 2.f * c3 * s3;

    u64 ZRa = pk2(zr0, zr1), ZIa = pk2(zi0, zi1);
    u64 ZRb = pk2(zr2, zr3), ZIb = pk2(zi2, zi3);
    u64 Ya  = pk2(2.f * zr0, 2.f * zr1);           // 2*Re(z)
    u64 Yb  = pk2(2.f * zr2, 2.f * zr3);
    u64 CWRa = pk2(c0, c1), CWIa = pk2(-s0, -s1);  // conj(w)
    u64 CWRb = pk2(c2, c3), CWIb = pk2(-s2, -s3);

    // Goertzel init: b_127 = C_127, b_128 = 0
    u64 B1ra, B1ia;
    lds_v2b64(B1ra, B1ia, sbase + 16u * DEG);
    u64 B1rb = B1ra, B1ib = B1ia;
    u64 B2ra = 0, B2ia = 0, B2rb = 0, B2ib = 0;

#pragma unroll 8
    for (int k = DEG - 1; k >= 0; k--) {
        u64 CR, CI;
        lds_v2b64(CR, CI, sbase + 16u * (unsigned)k);
        // chain a
        u64 tra = fsub2(CR, B2ra);
        u64 tia = fsub2(CI, B2ia);
        u64 nra = ffma2(Ya, B1ra, tra);
        u64 nia = ffma2(Ya, B1ia, tia);
        B2ra = B1ra; B2ia = B1ia; B1ra = nra; B1ia = nia;
        // chain b
        u64 trb = fsub2(CR, B2rb);
        u64 tib = fsub2(CI, B2ib);
        u64 nrb = ffma2(Yb, B1rb, trb);
        u64 nib = ffma2(Yb, B1ib, tib);
        B2rb = B1rb; B2ib = B1ib; B1rb = nrb; B1ib = nib;
    }
    // Now B1 = b_0, B2 = b_1.  P = b_0 - conj(z)*b_1
    // re(conj(z)*b1) = zr*b1r + zi*b1i ; im = zr*b1i - zi*b1r
    u64 qra = ffma2(ZRa, B2ra, fmul2(ZIa, B2ia));
    u64 qia = ffma2(ZRa, B2ia, neg2(fmul2(ZIa, B2ra)));
    u64 Pra = fsub2(B1ra, qra);
    u64 Pia = fsub2(B1ia, qia);
    u64 qrb = ffma2(ZRb, B2rb, fmul2(ZIb, B2ib));
    u64 qib = ffma2(ZRb, B2ib, neg2(fmul2(ZIb, B2rb)));
    u64 Prb = fsub2(B1rb, qrb);
    u64 Pib = fsub2(B1ib, qib);

    // w^-127 = conj(w) * conj(z)^63 ;  63 = 111111b -> r=v; 5x { v=v^2; r=r*v }
    u64 VRa = ZRa, VIa = neg2(ZIa), RRa = VRa, RIa = VIa;
    u64 VRb = ZRb, VIb = neg2(ZIb), RRb = VRb, RIb = VIb;
#pragma unroll
    for (int q = 0; q < 5; q++) {
        u64 nvr, nvi;
        cmul2(nvr, nvi, VRa, VIa, VRa, VIa); VRa = nvr; VIa = nvi;
        cmul2(nvr, nvi, RRa, RIa, VRa, VIa); RRa = nvr; RIa = nvi;
        cmul2(nvr, nvi, VRb, VIb, VRb, VIb); VRb = nvr; VIb = nvi;
        cmul2(nvr, nvi, RRb, RIb, VRb, VIb); RRb = nvr; RIb = nvi;
    }
    u64 MRa, MIa, MRb, MIb;
    cmul2(MRa, MIa, CWRa, CWIa, RRa, RIa);
    cmul2(MRb, MIb, CWRb, CWIb, RRb, RIb);
    // final = P * M
    u64 FRa, FIa, FRb, FIb;
    cmul2(FRa, FIa, Pra, Pia, MRa, MIa);
    cmul2(FRb, FIb, Prb, Pib, MRb, MIb);

    float r0, r1, r2, r3, i0, i1, i2, i3;
    upk2(FRa, r0, r1); upk2(FRb, r2, r3);
    upk2(FIa, i0, i1); upk2(FIb, i2, i3);

    *(float4*)(out + base)     = make_float4(r0, r1, r2, r3);  // real block
    *(float4*)(out + B + base) = make_float4(i0, i1, i2, i3);  // imag block
}

extern "C" void kernel_launch(void* const* d_in, const int* in_sizes, int n_in,
                              void* d_out, int out_size) {
    const float* th   = (const float*)d_in[0];
    const float* phis = (const float*)d_in[1];
    float* out = (float*)d_out;
    int B = in_sizes[0];

    qsp_coeff_kernel<<<1, NPHI>>>(phis);

    int nthreads = (B + 3) / 4;                 // 4 thetas per thread
    int blocks = (nthreads + 255) / 256;
    qsp_main_kernel<<<blocks, 256>>>(th, out, B);
}